// round 1
// baseline (speedup 1.0000x reference)
#include <cuda_runtime.h>
#include <cuda_bf16.h>

#define BATCH   2
#define CH      256
#define FH      96
#define FW      96
#define FHW     (FH * FW)
#define POOLED  7
#define NBINS   (POOLED * POOLED)
#define N_ROIS  512
#define SPATIAL_SCALE 0.0625f
#define TRANS_STD     0.1f

// NHWC scratch copy of the feature map: 2*96*96*256 floats = 18.9 MB (fits L2)
__device__ float g_feat_hwc[BATCH * FHW * CH];

// ---------------------------------------------------------------------------
// Transpose NCHW -> NHWC via 32x32 shared-memory tiles (coalesced both ways).
// Per batch: A[C][HW] -> B[HW][C].  HW=9216=288*32, C=256=8*32, exact tiling.
// ---------------------------------------------------------------------------
__global__ __launch_bounds__(256) void nchw_to_nhwc_kernel(const float* __restrict__ in) {
    __shared__ float tile[32][33];
    const int b   = blockIdx.z;
    const int hw0 = blockIdx.x * 32;
    const int c0  = blockIdx.y * 32;

    const float* src = in + (size_t)b * CH * FHW;
    #pragma unroll
    for (int j = 0; j < 32; j += 8) {
        int c  = c0 + threadIdx.y + j;
        int hw = hw0 + threadIdx.x;
        tile[threadIdx.y + j][threadIdx.x] = src[(size_t)c * FHW + hw];
    }
    __syncthreads();
    float* dst = g_feat_hwc + (size_t)b * FHW * CH;
    #pragma unroll
    for (int j = 0; j < 32; j += 8) {
        int hw = hw0 + threadIdx.y + j;
        int c  = c0 + threadIdx.x;
        dst[(size_t)hw * CH + c] = tile[threadIdx.x][threadIdx.y + j];
    }
}

// ---------------------------------------------------------------------------
// Deformable PS-RoI pooling.
// One CTA per (roi, bin); 256 threads = one channel each.
// Coordinate math is uniform per CTA; gathers are coalesced 1KB reads in NHWC.
// ---------------------------------------------------------------------------
__global__ __launch_bounds__(256) void dpsroi_pool_kernel(
    const float* __restrict__ rois,     // [N_ROIS, 5]
    const float* __restrict__ trans,    // [N_ROIS, 2, 7, 7]
    float* __restrict__ out)            // [N_ROIS, CH, 7, 7]
{
    const int bin = blockIdx.x;         // 0..48
    const int n   = blockIdx.y;         // roi index
    const int ph  = bin / POOLED;
    const int pw  = bin % POOLED;
    const int c   = threadIdx.x;        // channel

    const float* roi = rois + n * 5;
    const int   bidx = (int)roi[0];
    // jnp.round == round-half-to-even == rintf
    const float x1 = rintf(roi[1]) * SPATIAL_SCALE - 0.5f;
    const float y1 = rintf(roi[2]) * SPATIAL_SCALE - 0.5f;
    const float x2 = (rintf(roi[3]) + 1.0f) * SPATIAL_SCALE - 0.5f;
    const float y2 = (rintf(roi[4]) + 1.0f) * SPATIAL_SCALE - 0.5f;
    const float rw = fmaxf(x2 - x1, 0.1f);
    const float rh = fmaxf(y2 - y1, 0.1f);
    const float bin_w = rw * (1.0f / POOLED);
    const float bin_h = rh * (1.0f / POOLED);
    const float sub_w = bin_w * 0.5f;
    const float sub_h = bin_h * 0.5f;

    const float tx = trans[((size_t)n * 2 + 0) * NBINS + bin] * TRANS_STD;
    const float ty = trans[((size_t)n * 2 + 1) * NBINS + bin] * TRANS_STD;

    const float wstart = (float)pw * bin_w + x1 + tx * rw;
    const float hstart = (float)ph * bin_h + y1 + ty * rh;

    const float* feat = g_feat_hwc + (size_t)bidx * FHW * CH;

    float acc = 0.0f;
    int count = 0;

    #pragma unroll
    for (int iy = 0; iy < 2; iy++) {
        #pragma unroll
        for (int ix = 0; ix < 2; ix++) {
            const float w = wstart + (float)ix * sub_w;
            const float h = hstart + (float)iy * sub_h;
            // Uniform per CTA -> no divergence
            const bool valid = (w >= -0.5f) && (w <= (float)FW - 0.5f) &&
                               (h >= -0.5f) && (h <= (float)FH - 0.5f);
            if (!valid) continue;
            count++;
            const float wc = fminf(fmaxf(w, 0.0f), (float)FW - 1.0f);
            const float hc = fminf(fmaxf(h, 0.0f), (float)FH - 1.0f);
            const float x0f = floorf(wc);
            const float y0f = floorf(hc);
            const float dx = wc - x0f;
            const float dy = hc - y0f;
            const int x0i = (int)x0f;
            const int y0i = (int)y0f;
            const int x1i = (int)ceilf(wc);
            const int y1i = (int)ceilf(hc);

            const float* r0 = feat + (size_t)y0i * FW * CH;
            const float* r1 = feat + (size_t)y1i * FW * CH;
            const float f00 = __ldg(r0 + (size_t)x0i * CH + c);
            const float f01 = __ldg(r0 + (size_t)x1i * CH + c);
            const float f10 = __ldg(r1 + (size_t)x0i * CH + c);
            const float f11 = __ldg(r1 + (size_t)x1i * CH + c);

            const float w00 = (1.0f - dx) * (1.0f - dy);
            const float w01 = dx * (1.0f - dy);
            const float w10 = (1.0f - dx) * dy;
            const float w11 = dx * dy;
            acc += w00 * f00 + w01 * f01 + w10 * f10 + w11 * f11;
        }
    }

    const float result = (count > 0) ? (acc / (float)count) : 0.0f;
    out[(((size_t)n * CH + c) * POOLED + ph) * POOLED + pw] = result;
}

extern "C" void kernel_launch(void* const* d_in, const int* in_sizes, int n_in,
                              void* d_out, int out_size)
{
    const float* bottom_data  = (const float*)d_in[0];  // (2,256,96,96)
    const float* bottom_rois  = (const float*)d_in[1];  // (512,5)
    const float* bottom_trans = (const float*)d_in[2];  // (512,2,7,7)
    float* out = (float*)d_out;                         // (512,256,7,7)

    {
        dim3 tb(32, 8);
        dim3 tg(FHW / 32, CH / 32, BATCH);
        nchw_to_nhwc_kernel<<<tg, tb>>>(bottom_data);
    }
    {
        dim3 pg(NBINS, N_ROIS);
        dpsroi_pool_kernel<<<pg, 256>>>(bottom_rois, bottom_trans, out);
    }
}

// round 2
// speedup vs baseline: 1.7543x; 1.7543x over previous
#include <cuda_runtime.h>
#include <cuda_bf16.h>

#define BATCH   2
#define CH      256
#define FH      96
#define FW      96
#define FHW     (FH * FW)
#define POOLED  7
#define NBINS   (POOLED * POOLED)
#define N_ROIS  512
#define SPATIAL_SCALE 0.0625f
#define TRANS_STD     0.1f

#define CH_HALF 128          // channels per CTA
#define BINS_PER_ITER 8      // 256 threads / 32 threads-per-bin

// NHWC scratch copy of the feature map: 2*96*96*256 floats = 18.9 MB (fits L2)
__device__ __align__(128) float g_feat_hwc[BATCH * FHW * CH];

// ---------------------------------------------------------------------------
// Transpose NCHW -> NHWC via 32x32 shared-memory tiles (coalesced both ways).
// ---------------------------------------------------------------------------
__global__ __launch_bounds__(256) void nchw_to_nhwc_kernel(const float* __restrict__ in) {
    __shared__ float tile[32][33];
    const int b   = blockIdx.z;
    const int hw0 = blockIdx.x * 32;
    const int c0  = blockIdx.y * 32;

    const float* src = in + (size_t)b * CH * FHW;
    #pragma unroll
    for (int j = 0; j < 32; j += 8) {
        int c  = c0 + threadIdx.y + j;
        int hw = hw0 + threadIdx.x;
        tile[threadIdx.y + j][threadIdx.x] = src[(size_t)c * FHW + hw];
    }
    __syncthreads();
    float* dst = g_feat_hwc + (size_t)b * FHW * CH;
    #pragma unroll
    for (int j = 0; j < 32; j += 8) {
        int hw = hw0 + threadIdx.y + j;
        int c  = c0 + threadIdx.x;
        dst[(size_t)hw * CH + c] = tile[threadIdx.x][threadIdx.y + j];
    }
}

// ---------------------------------------------------------------------------
// Deformable PS-RoI pooling, v2.
// Grid: (2 channel-halves, 512 rois). 256 threads.
//   warp  = one bin (32 threads x float4 = 128 channels)  -> uniform control
//   8 bins processed per loop iteration, 7 iterations cover 49 bins
// Results staged in smem in output layout, then one coalesced 25KB store.
// ---------------------------------------------------------------------------
__global__ __launch_bounds__(256) void dpsroi_pool_kernel(
    const float* __restrict__ rois,     // [N_ROIS, 5]
    const float* __restrict__ trans,    // [N_ROIS, 2, 7, 7]
    float* __restrict__ out)            // [N_ROIS, CH, 7, 7]
{
    __shared__ float s_out[CH_HALF * NBINS];   // 25088 B

    const int half = blockIdx.x;        // 0 or 1: channel half
    const int n    = blockIdx.y;        // roi index
    const int tid  = threadIdx.x;
    const int cg   = tid & 31;          // channel group within half (float4)
    const int bsub = tid >> 5;          // 0..7: bin sub-slot

    // --- per-roi params (uniform; cheap enough to compute in every thread) ---
    const float* roi = rois + n * 5;
    const int   bidx = (int)roi[0];
    const float x1 = rintf(roi[1]) * SPATIAL_SCALE - 0.5f;
    const float y1 = rintf(roi[2]) * SPATIAL_SCALE - 0.5f;
    const float x2 = (rintf(roi[3]) + 1.0f) * SPATIAL_SCALE - 0.5f;
    const float y2 = (rintf(roi[4]) + 1.0f) * SPATIAL_SCALE - 0.5f;
    const float rw = fmaxf(x2 - x1, 0.1f);
    const float rh = fmaxf(y2 - y1, 0.1f);
    const float bin_w = rw * (1.0f / POOLED);
    const float bin_h = rh * (1.0f / POOLED);
    const float sub_w = bin_w * 0.5f;
    const float sub_h = bin_h * 0.5f;

    // base pointer for this CTA's channel range, cast for float4 loads
    const float4* __restrict__ feat =
        (const float4*)(g_feat_hwc + (size_t)bidx * FHW * CH + half * CH_HALF) + cg;
    // NOTE: feat indexed in float4 units with stride CH/4 per spatial position

    const float* trans_n = trans + (size_t)n * 2 * NBINS;

    #pragma unroll 1
    for (int b0 = 0; b0 < NBINS; b0 += BINS_PER_ITER) {
        const int bin = b0 + bsub;
        if (bin < NBINS) {
            const int ph = bin / POOLED;
            const int pw = bin % POOLED;

            const float tx = __ldg(trans_n + bin) * TRANS_STD;
            const float ty = __ldg(trans_n + NBINS + bin) * TRANS_STD;

            const float wstart = (float)pw * bin_w + x1 + tx * rw;
            const float hstart = (float)ph * bin_h + y1 + ty * rh;

            float4 acc = make_float4(0.f, 0.f, 0.f, 0.f);
            int count = 0;

            #pragma unroll
            for (int iy = 0; iy < 2; iy++) {
                #pragma unroll
                for (int ix = 0; ix < 2; ix++) {
                    const float w = wstart + (float)ix * sub_w;
                    const float h = hstart + (float)iy * sub_h;
                    const bool valid = (w >= -0.5f) && (w <= (float)FW - 0.5f) &&
                                       (h >= -0.5f) && (h <= (float)FH - 0.5f);
                    if (!valid) continue;   // uniform per warp
                    count++;
                    const float wc = fminf(fmaxf(w, 0.0f), (float)FW - 1.0f);
                    const float hc = fminf(fmaxf(h, 0.0f), (float)FH - 1.0f);
                    const float x0f = floorf(wc);
                    const float y0f = floorf(hc);
                    const float dx = wc - x0f;
                    const float dy = hc - y0f;
                    const int x0i = (int)x0f;
                    const int y0i = (int)y0f;
                    const int x1i = (int)ceilf(wc);
                    const int y1i = (int)ceilf(hc);

                    const size_t r0 = (size_t)(y0i * FW) * (CH / 4);
                    const size_t r1 = (size_t)(y1i * FW) * (CH / 4);
                    const float4 f00 = __ldg(feat + r0 + (size_t)x0i * (CH / 4));
                    const float4 f01 = __ldg(feat + r0 + (size_t)x1i * (CH / 4));
                    const float4 f10 = __ldg(feat + r1 + (size_t)x0i * (CH / 4));
                    const float4 f11 = __ldg(feat + r1 + (size_t)x1i * (CH / 4));

                    const float w00 = (1.0f - dx) * (1.0f - dy);
                    const float w01 = dx * (1.0f - dy);
                    const float w10 = (1.0f - dx) * dy;
                    const float w11 = dx * dy;

                    acc.x += w00 * f00.x + w01 * f01.x + w10 * f10.x + w11 * f11.x;
                    acc.y += w00 * f00.y + w01 * f01.y + w10 * f10.y + w11 * f11.y;
                    acc.z += w00 * f00.z + w01 * f01.z + w10 * f10.z + w11 * f11.z;
                    acc.w += w00 * f00.w + w01 * f01.w + w10 * f10.w + w11 * f11.w;
                }
            }

            const float inv = (count > 0) ? (1.0f / (float)count) : 0.0f;
            const int cbase = cg * 4;
            s_out[(cbase + 0) * NBINS + bin] = acc.x * inv;
            s_out[(cbase + 1) * NBINS + bin] = acc.y * inv;
            s_out[(cbase + 2) * NBINS + bin] = acc.z * inv;
            s_out[(cbase + 3) * NBINS + bin] = acc.w * inv;
        }
    }

    __syncthreads();

    // Coalesced contiguous 25KB store: out region for (roi n, channels half)
    float* o = out + ((size_t)n * CH + (size_t)half * CH_HALF) * NBINS;
    #pragma unroll
    for (int i = tid; i < CH_HALF * NBINS; i += 256) {
        o[i] = s_out[i];
    }
}

extern "C" void kernel_launch(void* const* d_in, const int* in_sizes, int n_in,
                              void* d_out, int out_size)
{
    const float* bottom_data  = (const float*)d_in[0];  // (2,256,96,96)
    const float* bottom_rois  = (const float*)d_in[1];  // (512,5)
    const float* bottom_trans = (const float*)d_in[2];  // (512,2,7,7)
    float* out = (float*)d_out;                         // (512,256,7,7)

    {
        dim3 tb(32, 8);
        dim3 tg(FHW / 32, CH / 32, BATCH);
        nchw_to_nhwc_kernel<<<tg, tb>>>(bottom_data);
    }
    {
        dim3 pg(2, N_ROIS);
        dpsroi_pool_kernel<<<pg, 256>>>(bottom_rois, bottom_trans, out);
    }
}

// round 3
// speedup vs baseline: 1.8560x; 1.0580x over previous
#include <cuda_runtime.h>
#include <cuda_bf16.h>

#define BATCH   2
#define CH      256
#define CH4     (CH / 4)
#define FH      96
#define FW      96
#define FHW     (FH * FW)
#define POOLED  7
#define NBINS   (POOLED * POOLED)
#define N_ROIS  512
#define SPATIAL_SCALE 0.0625f
#define TRANS_STD     0.1f

#define CH_HALF 128          // channels per CTA
#define BINS_PER_ITER 8      // 256 threads / 32 threads-per-bin

// NHWC scratch copy of the feature map: 2*96*96*256 floats = 18.9 MB (fits L2)
__device__ __align__(128) float g_feat_hwc[BATCH * FHW * CH];

// ---------------------------------------------------------------------------
// Transpose NCHW -> NHWC via 32x32 shared-memory tiles (coalesced both ways).
// ---------------------------------------------------------------------------
__global__ __launch_bounds__(256) void nchw_to_nhwc_kernel(const float* __restrict__ in) {
    __shared__ float tile[32][33];
    const int b   = blockIdx.z;
    const int hw0 = blockIdx.x * 32;
    const int c0  = blockIdx.y * 32;

    const float* src = in + (size_t)b * CH * FHW;
    #pragma unroll
    for (int j = 0; j < 32; j += 8) {
        int c  = c0 + threadIdx.y + j;
        int hw = hw0 + threadIdx.x;
        tile[threadIdx.y + j][threadIdx.x] = src[(size_t)c * FHW + hw];
    }
    __syncthreads();
    float* dst = g_feat_hwc + (size_t)b * FHW * CH;
    #pragma unroll
    for (int j = 0; j < 32; j += 8) {
        int hw = hw0 + threadIdx.y + j;
        int c  = c0 + threadIdx.x;
        dst[(size_t)hw * CH + c] = tile[threadIdx.x][threadIdx.y + j];
    }
}

// ---------------------------------------------------------------------------
// Deformable PS-RoI pooling, v3: branch-free separable 4x4 stencil per bin.
// Grid: (2 channel-halves, 512 rois). 256 threads.
//   warp = one bin (32 threads x float4 = 128 channels)
// acc = sum_r ay[r] * sum_c ax[c] * F[row_r][col_c]
// with ay/ax = bilinear weight * validity  (separable mask), all 16 loads
// independent and batched -> high MLP, no divergence.
// ---------------------------------------------------------------------------
__global__ __launch_bounds__(256, 4) void dpsroi_pool_kernel(
    const float* __restrict__ rois,     // [N_ROIS, 5]
    const float* __restrict__ trans,    // [N_ROIS, 2, 7, 7]
    float* __restrict__ out)            // [N_ROIS, CH, 7, 7]
{
    __shared__ float s_out[CH_HALF * NBINS];   // 25088 B

    const int half = blockIdx.x;        // 0 or 1: channel half
    const int n    = blockIdx.y;        // roi index
    const int tid  = threadIdx.x;
    const int cg   = tid & 31;          // channel group within half (float4)
    const int bsub = tid >> 5;          // 0..7: bin sub-slot

    const float* roi = rois + n * 5;
    const int   bidx = (int)roi[0];
    const float x1 = rintf(roi[1]) * SPATIAL_SCALE - 0.5f;
    const float y1 = rintf(roi[2]) * SPATIAL_SCALE - 0.5f;
    const float x2 = (rintf(roi[3]) + 1.0f) * SPATIAL_SCALE - 0.5f;
    const float y2 = (rintf(roi[4]) + 1.0f) * SPATIAL_SCALE - 0.5f;
    const float rw = fmaxf(x2 - x1, 0.1f);
    const float rh = fmaxf(y2 - y1, 0.1f);
    const float bin_w = rw * (1.0f / POOLED);
    const float bin_h = rh * (1.0f / POOLED);
    const float sub_w = bin_w * 0.5f;
    const float sub_h = bin_h * 0.5f;

    const float4* __restrict__ feat =
        (const float4*)(g_feat_hwc + (size_t)bidx * FHW * CH + half * CH_HALF) + cg;

    const float* trans_n = trans + (size_t)n * 2 * NBINS;

    #pragma unroll 1
    for (int b0 = 0; b0 < NBINS; b0 += BINS_PER_ITER) {
        const int bin = b0 + bsub;
        if (bin < NBINS) {
            const int ph = bin / POOLED;
            const int pw = bin % POOLED;

            const float tx = __ldg(trans_n + bin) * TRANS_STD;
            const float ty = __ldg(trans_n + NBINS + bin) * TRANS_STD;

            const float wstart = (float)pw * bin_w + x1 + tx * rw;
            const float hstart = (float)ph * bin_h + y1 + ty * rh;

            // ---- per-axis sample math (branch-free) ----
            const float w0 = wstart, w1 = wstart + sub_w;
            const float h0 = hstart, h1 = hstart + sub_h;

            const float vx0 = (w0 >= -0.5f && w0 <= (float)FW - 0.5f) ? 1.0f : 0.0f;
            const float vx1 = (w1 >= -0.5f && w1 <= (float)FW - 0.5f) ? 1.0f : 0.0f;
            const float vy0 = (h0 >= -0.5f && h0 <= (float)FH - 0.5f) ? 1.0f : 0.0f;
            const float vy1 = (h1 >= -0.5f && h1 <= (float)FH - 0.5f) ? 1.0f : 0.0f;

            const float wc0 = fminf(fmaxf(w0, 0.0f), (float)FW - 1.0f);
            const float wc1 = fminf(fmaxf(w1, 0.0f), (float)FW - 1.0f);
            const float hc0 = fminf(fmaxf(h0, 0.0f), (float)FH - 1.0f);
            const float hc1 = fminf(fmaxf(h1, 0.0f), (float)FH - 1.0f);

            const float fx0 = floorf(wc0), fx1 = floorf(wc1);
            const float fy0 = floorf(hc0), fy1 = floorf(hc1);
            const float dx0 = wc0 - fx0, dx1 = wc1 - fx1;
            const float dy0 = hc0 - fy0, dy1 = hc1 - fy1;

            // column offsets (float4 units): 4 corner x-positions
            int colv[4];
            colv[0] = (int)fx0 * CH4;
            colv[1] = (int)ceilf(wc0) * CH4;
            colv[2] = (int)fx1 * CH4;
            colv[3] = (int)ceilf(wc1) * CH4;
            // row offsets: 4 corner y-positions
            int rowv[4];
            rowv[0] = (int)fy0 * (FW * CH4);
            rowv[1] = (int)ceilf(hc0) * (FW * CH4);
            rowv[2] = (int)fy1 * (FW * CH4);
            rowv[3] = (int)ceilf(hc1) * (FW * CH4);

            // separable coefficients: weight * validity
            float ax[4], ay[4];
            ax[0] = vx0 * (1.0f - dx0);  ax[1] = vx0 * dx0;
            ax[2] = vx1 * (1.0f - dx1);  ax[3] = vx1 * dx1;
            ay[0] = vy0 * (1.0f - dy0);  ay[1] = vy0 * dy0;
            ay[2] = vy1 * (1.0f - dy1);  ay[3] = vy1 * dy1;

            const float count = (vx0 + vx1) * (vy0 + vy1);
            const float inv = (count > 0.0f) ? (1.0f / count) : 0.0f;

            float4 acc = make_float4(0.f, 0.f, 0.f, 0.f);
            #pragma unroll
            for (int r = 0; r < 4; r++) {
                float4 rs = make_float4(0.f, 0.f, 0.f, 0.f);
                #pragma unroll
                for (int cc = 0; cc < 4; cc++) {
                    const float4 f = __ldg(feat + (size_t)(rowv[r] + colv[cc]));
                    rs.x += ax[cc] * f.x;
                    rs.y += ax[cc] * f.y;
                    rs.z += ax[cc] * f.z;
                    rs.w += ax[cc] * f.w;
                }
                acc.x += ay[r] * rs.x;
                acc.y += ay[r] * rs.y;
                acc.z += ay[r] * rs.z;
                acc.w += ay[r] * rs.w;
            }

            const int cbase = cg * 4;
            s_out[(cbase + 0) * NBINS + bin] = acc.x * inv;
            s_out[(cbase + 1) * NBINS + bin] = acc.y * inv;
            s_out[(cbase + 2) * NBINS + bin] = acc.z * inv;
            s_out[(cbase + 3) * NBINS + bin] = acc.w * inv;
        }
    }

    __syncthreads();

    // Coalesced contiguous 25KB store for (roi n, channel half)
    float* o = out + ((size_t)n * CH + (size_t)half * CH_HALF) * NBINS;
    #pragma unroll
    for (int i = tid; i < CH_HALF * NBINS; i += 256) {
        o[i] = s_out[i];
    }
}

extern "C" void kernel_launch(void* const* d_in, const int* in_sizes, int n_in,
                              void* d_out, int out_size)
{
    const float* bottom_data  = (const float*)d_in[0];  // (2,256,96,96)
    const float* bottom_rois  = (const float*)d_in[1];  // (512,5)
    const float* bottom_trans = (const float*)d_in[2];  // (512,2,7,7)
    float* out = (float*)d_out;                         // (512,256,7,7)

    {
        dim3 tb(32, 8);
        dim3 tg(FHW / 32, CH / 32, BATCH);
        nchw_to_nhwc_kernel<<<tg, tb>>>(bottom_data);
    }
    {
        dim3 pg(2, N_ROIS);
        dpsroi_pool_kernel<<<pg, 256>>>(bottom_rois, bottom_trans, out);
    }
}